// round 17
// baseline (speedup 1.0000x reference)
#include <cuda_runtime.h>
#include <cuda_fp16.h>
#include <cstdint>

#define BATCH 4096
#define NA 8
#define ND 11
#define NPOS 3584
#define ATOM 512
#define NS 4096
#define ROWS 32768          // BATCH*NA
#define QTILES 112          // tiles per position-quarter
#define QPOS 896            // positions per quarter
#define FRAGB (QTILES * 32 * 16)   // 57344 B fragments
#define BLB (QTILES * 4 * 8)       // 3584 B bl10
#define DSMEM (FRAGB + BLB)        // 60928 B

// Per-quarter partial keys, plain stores (no zeroing, no atomics needed)
__device__ unsigned long long g_part[4 * ROWS];

static __device__ __forceinline__ uint32_t h2pack(float x, float y) {
    __half2 h = __halves2half2(__float2half_rn(x), __float2half_rn(y));
    return *(uint32_t*)&h;
}
static __device__ __forceinline__ float hi16(float x) {
    return __half2float(__float2half_rn(x));
}

static __device__ __forceinline__ float v1s(const float* A, int k) {
    return (k <= 10) ? A[k] : A[k - 11];
}
static __device__ __forceinline__ float v2s(const float* A, int k) {
    return (k <= 10) ? (A[k] - hi16(A[k])) : A[k - 6];
}
static __device__ __forceinline__ void build_frags(const float* R0, const float* R1, int tig,
                                                   uint4& Af1, uint4& Af2) {
    const int k0 = tig * 2, ka = k0 + 8, kb = k0 + 9;
    Af1.x = h2pack(R0[k0], R0[k0 + 1]);
    Af1.y = h2pack(R1[k0], R1[k0 + 1]);
    Af1.z = h2pack(v1s(R0, ka), v1s(R0, kb));
    Af1.w = h2pack(v1s(R1, ka), v1s(R1, kb));
    Af2.x = h2pack(R0[k0] - hi16(R0[k0]), R0[k0 + 1] - hi16(R0[k0 + 1]));
    Af2.y = h2pack(R1[k0] - hi16(R1[k0]), R1[k0 + 1] - hi16(R1[k0 + 1]));
    Af2.z = h2pack(v2s(R0, ka), v2s(R0, kb));
    Af2.w = h2pack(v2s(R1, ka), v2s(R1, kb));
}

// Fused dual-mma, read-write accumulators preloaded with the a10*bl10 correction.
static __device__ __forceinline__ void mma2x(float* d, const uint4& a1, const uint4& a2,
                                             const uint4& F) {
    asm volatile(
        "mma.sync.aligned.m16n8k16.row.col.f32.f16.f16.f32 "
        "{%0,%1,%2,%3}, {%4,%5,%6,%7}, {%12,%13}, {%0,%1,%2,%3};\n\t"
        "mma.sync.aligned.m16n8k16.row.col.f32.f16.f16.f32 "
        "{%0,%1,%2,%3}, {%8,%9,%10,%11}, {%14,%15}, {%0,%1,%2,%3};"
        : "+f"(d[0]), "+f"(d[1]), "+f"(d[2]), "+f"(d[3])
        : "r"(a1.x), "r"(a1.y), "r"(a1.z), "r"(a1.w),
          "r"(a2.x), "r"(a2.y), "r"(a2.z), "r"(a2.w),
          "r"(F.x), "r"(F.y), "r"(F.z), "r"(F.w));
}

// ---- Phase 1 (self-contained): build B fragments for this quarter in SMEM,
// normalize A rows, run 2-HMMA packed split-fp16 GEMM with streaming argmax,
// emit per-quarter partial keys with plain stores. ----
__global__ void __launch_bounds__(256, 2) argmax_kernel(const float* __restrict__ index,
                                                        const float* __restrict__ positions) {
    extern __shared__ char dsm[];       // frag 57344 | bl10 3584
    __shared__ float sAn[256][16];      // exact normalized A rows (16 KB)

    const int tid = threadIdx.x;
    const int lane = tid & 31;
    const int qtr = blockIdx.x & 3;
    const int oct = blockIdx.x >> 2;    // 256-row block id
    const int w = tid >> 5;
    const int g = lane >> 2, tig = lane & 3;

    uint4* fr_w = (uint4*)dsm;
    float* bl_w = (float*)(dsm + FRAGB);

    // build this quarter's B fragments + bl10 directly in SMEM (prep folded in)
    for (int e = tid; e < QTILES * 32; e += 256) {
        int tile = e >> 5, le = e & 31;
        int ge = le >> 2, tige = le & 3;
        int p = qtr * QPOS + tile * 8 + ge;
        const float* pp = positions + (size_t)p * ND;
        float v[ND], acc = 0.0f;
#pragma unroll
        for (int d = 0; d < ND; d++) { v[d] = pp[d]; acc = fmaf(v[d], v[d], acc); }
        float nrm = sqrtf(acc);
        float nb[ND], lb[ND];
#pragma unroll
        for (int d = 0; d < ND; d++) {
            nb[d] = v[d] / nrm;
            lb[d] = nb[d] - hi16(nb[d]);
        }
        int k0 = tige * 2;
        int ka = k0 + 8, kb = k0 + 9;
        float b1a = (ka <= 10) ? nb[ka] : lb[ka - 11];
        float b1b = (kb <= 10) ? nb[kb] : lb[kb - 11];
        float b2a = (ka <= 10) ? nb[ka] : lb[ka - 6];
        float b2b = (kb <= 10) ? nb[kb] : lb[kb - 6];
        fr_w[e] = make_uint4(h2pack(nb[k0], nb[k0 + 1]), h2pack(b1a, b1b),
                             h2pack(nb[k0], nb[k0 + 1]), h2pack(b2a, b2b));
        if (tige == 0)  // one writer per position: bl10 at [ge>>1][tile][ge&1]
            bl_w[((ge >> 1) * QTILES + tile) * 2 + (ge & 1)] = lb[10];
    }

    {   // normalize this CTA's 256 A rows (reference op order)
        int row = oct * 256 + tid;
        const float* ip = index + (size_t)row * ND;
        float v[ND], acc = 0.0f;
#pragma unroll
        for (int d = 0; d < ND; d++) { v[d] = ip[d]; acc = fmaf(v[d], v[d], acc); }
        float nrm = sqrtf(acc);
#pragma unroll
        for (int d = 0; d < 16; d++) sAn[tid][d] = (d < ND) ? (v[d] / nrm) : 0.0f;
    }
    __syncthreads();

    const float* Ra0 = sAn[w * 32 + g];
    const float* Ra1 = sAn[w * 32 + g + 8];
    const float* Rb0 = sAn[w * 32 + 16 + g];
    const float* Rb1 = sAn[w * 32 + 24 + g];
    const float a10[4] = {Ra0[10], Ra1[10], Rb0[10], Rb1[10]};

    uint4 Af1a, Af2a, Af1b, Af2b;
    build_frags(Ra0, Ra1, tig, Af1a, Af2a);
    build_frags(Rb0, Rb1, tig, Af1b, Af2b);

    const uint4* fr = (const uint4*)dsm;
    const float4* c4 = (const float4*)((const float2*)(dsm + FRAGB) + tig * QTILES);

    float best[4] = {-1e30f, -1e30f, -1e30f, -1e30f};
    float bs0[4] = {-1e30f, -1e30f, -1e30f, -1e30f};
    int bt[4] = {0, 0, 0, 0};

#pragma unroll 4
    for (int t = 0; t < QTILES; t += 2) {
        uint4 F0 = fr[t * 32 + lane];
        uint4 F1 = fr[(t + 1) * 32 + lane];
        float4 cc = c4[t >> 1];

        {   // tile t
            float da[4] = {a10[0] * cc.x, a10[0] * cc.y, a10[1] * cc.x, a10[1] * cc.y};
            float db[4] = {a10[2] * cc.x, a10[2] * cc.y, a10[3] * cc.x, a10[3] * cc.y};
            mma2x(da, Af1a, Af2a, F0);
            mma2x(db, Af1b, Af2b, F0);
#pragma unroll
            for (int r = 0; r < 4; r++) {
                float s0 = (r < 2) ? da[r * 2] : db[(r - 2) * 2];
                float s1 = (r < 2) ? da[r * 2 + 1] : db[(r - 2) * 2 + 1];
                float m = fmaxf(s0, s1);
                if (m > best[r]) { best[r] = m; bt[r] = t; bs0[r] = s0; }
            }
        }
        {   // tile t+1
            float da[4] = {a10[0] * cc.z, a10[0] * cc.w, a10[1] * cc.z, a10[1] * cc.w};
            float db[4] = {a10[2] * cc.z, a10[2] * cc.w, a10[3] * cc.z, a10[3] * cc.w};
            mma2x(da, Af1a, Af2a, F1);
            mma2x(db, Af1b, Af2b, F1);
#pragma unroll
            for (int r = 0; r < 4; r++) {
                float s0 = (r < 2) ? da[r * 2] : db[(r - 2) * 2];
                float s1 = (r < 2) ? da[r * 2 + 1] : db[(r - 2) * 2 + 1];
                float m = fmaxf(s0, s1);
                if (m > best[r]) { best[r] = m; bt[r] = t + 1; bs0[r] = s0; }
            }
        }
    }

    // resolve deferred sub-index, pack keys, reduce over tig lanes
    unsigned long long key[4];
#pragma unroll
    for (int r = 0; r < 4; r++) {
        int sub = (best[r] != bs0[r]) ? 1 : 0;
        int bi = qtr * QPOS + bt[r] * 8 + tig * 2 + sub;
        unsigned u = __float_as_uint(best[r]);
        u = (u & 0x80000000u) ? ~u : (u | 0x80000000u);
        key[r] = ((unsigned long long)u << 32) | (unsigned)(NPOS - 1 - bi);
    }
#pragma unroll
    for (int sft = 1; sft <= 2; sft <<= 1) {
#pragma unroll
        for (int r = 0; r < 4; r++) {
            unsigned long long o = __shfl_xor_sync(0xFFFFFFFFu, key[r], sft);
            if (o > key[r]) key[r] = o;
        }
    }
    if (tig == 0) {  // plain per-quarter partial stores (no atomics, no init pass)
        int rbase = oct * 256 + w * 32;
        unsigned long long* part = g_part + (size_t)qtr * ROWS;
        part[rbase + g] = key[0];
        part[rbase + g + 8] = key[1];
        part[rbase + 16 + g] = key[2];
        part[rbase + 24 + g] = key[3];
    }
}

// ---- Phase 2: merge quarter-keys, column-owner scatter, int_index, passthrough ----
__global__ void __launch_bounds__(512) scatter_kernel(const float* __restrict__ atoms,
                                                      const float* __restrict__ index,
                                                      float* __restrict__ out) {
    __shared__ float buf[NS];
    __shared__ int offs[NA];
    const int tid = threadIdx.x;

    {   // passthrough copy of raw index
        int i = blockIdx.x * 512 + tid;
        if (i < ROWS * ND / 4)
            ((float4*)(out + ROWS + (size_t)BATCH * NS))[i] = ((const float4*)index)[i];
    }

#pragma unroll 1
    for (int bi = 0; bi < 4; bi++) {
        const int b = blockIdx.x * 4 + bi;
        __syncthreads();
        if (tid < NA) {
            int row = b * NA + tid;
            unsigned long long k = g_part[row];
#pragma unroll
            for (int q = 1; q < 4; q++) {
                unsigned long long o = g_part[(size_t)q * ROWS + row];
                if (o > k) k = o;
            }
            int idx = NPOS - 1 - (int)(unsigned)(k & 0xFFFFFFFFull);
            offs[tid] = idx;
            out[row] = (float)idx;
        }
#pragma unroll
        for (int c = 0; c < 8; c++) buf[c * 512 + tid] = 0.0f;
        __syncthreads();

#pragma unroll
        for (int a = 0; a < NA; a++) {
            int off = offs[a];
            int c0 = off >> 9, r = off & 511;
            if (tid >= r)
                buf[c0 * 512 + tid] += __ldg(atoms + a * ATOM + tid - r);
            else
                buf[(c0 + 1) * 512 + tid] += __ldg(atoms + a * ATOM + 512 - r + tid);
        }

        float* ob = out + ROWS + (size_t)b * NS;
#pragma unroll
        for (int c = 0; c < 8; c++) ob[c * 512 + tid] = buf[c * 512 + tid];
    }
}

extern "C" void kernel_launch(void* const* d_in, const int* in_sizes, int n_in,
                              void* d_out, int out_size) {
    const float* index = (const float*)d_in[0];      // (4096, 8, 11)
    const float* positions = (const float*)d_in[1];  // (3584, 11)
    const float* atoms = (const float*)d_in[2];      // (8, 512)
    float* out = (float*)d_out;  // [int_index(32768) | output(16777216) | index(360448)]

    cudaFuncSetAttribute(argmax_kernel, cudaFuncAttributeMaxDynamicSharedMemorySize, DSMEM);
    argmax_kernel<<<(ROWS / 256) * 4, 256, DSMEM>>>(index, positions);

    scatter_kernel<<<BATCH / 4, 512>>>(atoms, index, out);
}